// round 11
// baseline (speedup 1.0000x reference)
#include <cuda_runtime.h>
#include <cuda_bf16.h>
#include <math.h>
#include <stdint.h>

#define BATCH 4
#define CDIM  512
#define NPIX  4096
#define NPC   (BATCH * NPIX)
#define SEL_TH 15.0f          // candidate selection window below approx max
#define PVW    2e-6f          // PV weight prune threshold

// ---------------- scratch (device globals; device-code access ONLY) --------
__device__ float g_mean[3][CDIM];
__device__ float g_inv[3][CDIM];
__device__ float g_b3[3][CDIM];                                      // biases (folded f,g; raw h)
__device__ __align__(256) __nv_bfloat16 g_Wh3[3][CDIM * CDIM];       // weights hi
__device__ __align__(256) __nv_bfloat16 g_Wl3[3][CDIM * CDIM];       // weights lo
__device__ __align__(256) __nv_bfloat16 g_Xh[(size_t)3 * BATCH * NPIX * CDIM];  // inputs [t][b][n][c] hi
__device__ __align__(256) __nv_bfloat16 g_Xl[(size_t)3 * BATCH * NPIX * CDIM];  // inputs lo
__device__ __align__(256) __nv_bfloat16 g_Qh[(size_t)BATCH * NPIX * CDIM];   // [b][n][c]
__device__ __align__(256) __nv_bfloat16 g_Ql[(size_t)BATCH * NPIX * CDIM];
__device__ __align__(256) __nv_bfloat16 g_Kh[(size_t)BATCH * NPIX * CDIM];
__device__ __align__(256) __nv_bfloat16 g_Kl[(size_t)BATCH * NPIX * CDIM];
__device__ float g_Vf[(size_t)BATCH * NPIX * CDIM];    // V [b][m][v] fp32
__device__ __align__(256) __nv_bfloat16 g_Sh[(size_t)BATCH * NPIX * NPIX];  // hh scores bf16

// ---------------- PTX helpers (baseline sm_80+ instructions only) ----------
__device__ __forceinline__ uint32_t smem_to_u32(const void* p) {
    uint32_t a;
    asm("{ .reg .u64 t; cvta.to.shared.u64 t, %1; cvt.u32.u64 %0, t; }" : "=r"(a) : "l"(p));
    return a;
}
__device__ __forceinline__ void ldmx4(uint32_t* r, uint32_t addr) {
    asm volatile("ldmatrix.sync.aligned.m8n8.x4.shared.b16 {%0,%1,%2,%3}, [%4];"
                 : "=r"(r[0]), "=r"(r[1]), "=r"(r[2]), "=r"(r[3]) : "r"(addr));
}
__device__ __forceinline__ void mma16816(float* c, const uint32_t* a, const uint32_t* b) {
    asm volatile("mma.sync.aligned.m16n8k16.row.col.f32.bf16.bf16.f32 "
                 "{%0,%1,%2,%3},{%4,%5,%6,%7},{%8,%9},{%0,%1,%2,%3};"
                 : "+f"(c[0]), "+f"(c[1]), "+f"(c[2]), "+f"(c[3])
                 : "r"(a[0]), "r"(a[1]), "r"(a[2]), "r"(a[3]), "r"(b[0]), "r"(b[1]));
}
__device__ __forceinline__ void cpasync16(uint32_t saddr, const void* g) {
    asm volatile("cp.async.cg.shared.global [%0], [%1], 16;" :: "r"(saddr), "l"(g));
}
#define CP_COMMIT() asm volatile("cp.async.commit_group;" ::: "memory")
#define CP_WAIT1()  asm volatile("cp.async.wait_group 1;" ::: "memory")
#define CP_WAIT0()  asm volatile("cp.async.wait_group 0;" ::: "memory")

// ---------------- reductions / split ----------------
__device__ __forceinline__ float warpSum(float v) {
    #pragma unroll
    for (int o = 16; o; o >>= 1) v += __shfl_down_sync(0xffffffffu, v, o);
    return v;
}
__device__ __forceinline__ float warpMax(float v) {
    #pragma unroll
    for (int o = 16; o; o >>= 1) v = fmaxf(v, __shfl_down_sync(0xffffffffu, v, o));
    return v;
}
__device__ __forceinline__ int warpInclScan(int v, int lane) {
    #pragma unroll
    for (int o = 1; o < 32; o <<= 1) {
        int t = __shfl_up_sync(0xffffffffu, v, o);
        if (lane >= o) v += t;
    }
    return v;
}
__device__ __forceinline__ void split2(float v, __nv_bfloat16& h, __nv_bfloat16& l) {
    h = __float2bfloat16(v);
    l = __float2bfloat16(v - __bfloat162float(h));
}
__device__ __forceinline__ void store_pair(__nv_bfloat16* H, __nv_bfloat16* L,
                                           size_t idx, float a, float b) {
    __nv_bfloat16 h0, l0, h1, l1;
    split2(a, h0, l0); split2(b, h1, l1);
    __nv_bfloat162 hh; hh.x = h0; hh.y = h1;
    __nv_bfloat162 ll; ll.x = l0; ll.y = l1;
    *(__nv_bfloat162*)(H + idx) = hh;
    *(__nv_bfloat162*)(L + idx) = ll;
}

// ---------------- 1) channel stats ----------------
__global__ void stats_kernel(const float* __restrict__ x0,
                             const float* __restrict__ x1,
                             const float* __restrict__ x2) {
    int c = blockIdx.x, t = blockIdx.y;
    const float* x = (t == 0) ? x0 : (t == 1 ? x1 : x2);
    float s = 0.f, ss = 0.f;
    for (int b = 0; b < BATCH; b++) {
        const float* p = x + ((size_t)b * CDIM + c) * NPIX;
        for (int i = threadIdx.x * 4; i < NPIX; i += blockDim.x * 4) {
            float4 v = *(const float4*)(p + i);
            s  += v.x + v.y + v.z + v.w;
            ss += v.x * v.x + v.y * v.y + v.z * v.z + v.w * v.w;
        }
    }
    __shared__ float sh1[8], sh2[8];
    int lane = threadIdx.x & 31, w = threadIdx.x >> 5;
    s = warpSum(s); ss = warpSum(ss);
    if (lane == 0) { sh1[w] = s; sh2[w] = ss; }
    __syncthreads();
    if (w == 0) {
        s  = (lane < (blockDim.x >> 5)) ? sh1[lane] : 0.f;
        ss = (lane < (blockDim.x >> 5)) ? sh2[lane] : 0.f;
        s = warpSum(s); ss = warpSum(ss);
        if (lane == 0) {
            float mean = s / (float)NPC;
            float var  = fmaxf(ss - s * mean, 0.f) / (float)(NPC - 1);
            g_mean[t][c] = mean;
            g_inv[t][c]  = 1.f / (sqrtf(var) + 1e-12f);
        }
    }
}

// ---------------- 2) fold norm into weights, emit bf16 hi/lo ---------------
__global__ void fold_kernel(const float* __restrict__ Wf, const float* __restrict__ bf,
                            const float* __restrict__ Wg, const float* __restrict__ bg,
                            const float* __restrict__ Wh, const float* __restrict__ bh) {
    int o = blockIdx.x, t = blockIdx.y;
    const float* W  = (t == 0) ? Wf : (t == 1) ? Wg : Wh;
    const float* bb = (t == 0) ? bf : (t == 1) ? bg : bh;
    float acc = 0.f;
    for (int c = threadIdx.x; c < CDIM; c += blockDim.x) {
        float w = W[(size_t)o * CDIM + c];
        if (t < 2) w *= g_inv[t][c];
        __nv_bfloat16 h, l;
        split2(w, h, l);
        g_Wh3[t][(size_t)o * CDIM + c] = h;
        g_Wl3[t][(size_t)o * CDIM + c] = l;
        if (t < 2) acc += w * g_mean[t][c];
    }
    if (t == 2) {
        if (threadIdx.x == 0) g_b3[2][o] = bb[o];
        return;
    }
    __shared__ float sh[8];
    int lane = threadIdx.x & 31, w2 = threadIdx.x >> 5;
    acc = warpSum(acc);
    if (lane == 0) sh[w2] = acc;
    __syncthreads();
    if (w2 == 0) {
        acc = (lane < (blockDim.x >> 5)) ? sh[lane] : 0.f;
        acc = warpSum(acc);
        if (lane == 0) g_b3[t][o] = bb[o] - acc;
    }
}

// ---------------- 3a) transpose+split inputs: [b][c][n] f32 -> [t][b][n][c] bf16 hi/lo
__global__ void transpose_split_kernel(const float* __restrict__ x0,
                                       const float* __restrict__ x1,
                                       const float* __restrict__ x2) {
    __shared__ float tile[32][33];
    int z = blockIdx.z;
    int t = z >> 2, b = z & 3;
    const float* X = (t == 0) ? x0 : (t == 1) ? x1 : x2;
    int n0 = blockIdx.x * 32, c0 = blockIdx.y * 32;
    int tx = threadIdx.x, ty = threadIdx.y;
    #pragma unroll
    for (int i = 0; i < 4; i++)
        tile[ty + i * 8][tx] = X[((size_t)b * CDIM + c0 + ty + i * 8) * NPIX + n0 + tx];
    __syncthreads();
    #pragma unroll
    for (int i = 0; i < 4; i++) {
        float v = tile[tx][ty + i * 8];
        __nv_bfloat16 h, l;
        split2(v, h, l);
        size_t idx = (((size_t)(t * BATCH + b)) * NPIX + n0 + ty + i * 8) * CDIM + c0 + tx;
        g_Xh[idx] = h;
        g_Xl[idx] = l;
    }
}

// ---------------- shared tile constants ------------------------------------
#define MM_PITCH 40
#define MM_TELEM (128 * MM_PITCH)
#define MM_SMEM4 (3 * 4 * MM_TELEM * 2)    // 122880 bytes (4 tiles, 3 buf)
#define MM_SMEM2 (3 * 2 * MM_TELEM * 2)    // 61440 bytes  (2 tiles, 3 buf)

// ---------------- 3b) projection GEMM, 3-stage cp.async pipeline -----------
__global__ void __launch_bounds__(256, 1) projmma3_kernel() {
    extern __shared__ __align__(16) char smem2[];
    const int z = blockIdx.z;
    const int mode = z >> 2, b = z & 3;
    const int n0 = blockIdx.x * 128;
    const int o0 = blockIdx.y * 128;

    const int pitch = CDIM, nChunks = CDIM / 32;
    const __nv_bfloat16* Ahp = g_Xh + (((size_t)(mode * BATCH + b)) * NPIX + n0) * CDIM;
    const __nv_bfloat16* Alp = g_Xl + (((size_t)(mode * BATCH + b)) * NPIX + n0) * CDIM;
    const __nv_bfloat16* Bhp = g_Wh3[mode] + (size_t)o0 * CDIM;
    const __nv_bfloat16* Blp = g_Wl3[mode] + (size_t)o0 * CDIM;
    const float* bias = g_b3[mode];

    const uint32_t sb = smem_to_u32(smem2);
    const int tid = threadIdx.x;
    const int lane = tid & 31, wid = tid >> 5;
    const int wm = wid >> 2, wn = wid & 3;

    const __nv_bfloat16* ptrs[4] = {Ahp, Alp, Bhp, Blp};
    auto prefetch = [&](int buf, int c) {
        int col0 = c * 32;
        #pragma unroll
        for (int t4 = 0; t4 < 4; t4++) {
            #pragma unroll
            for (int s = 0; s < 2; s++) {
                int sidx = tid + s * 256;
                int row = sidx >> 2, cs = (sidx & 3) * 8;
                const void* g = ptrs[t4] + (size_t)row * pitch + col0 + cs;
                uint32_t sa = sb + (uint32_t)((((buf * 4 + t4) * MM_TELEM) + row * MM_PITCH + cs) * 2);
                cpasync16(sa, g);
            }
        }
    };

    float acc[4][4][4];
    #pragma unroll
    for (int i = 0; i < 4; i++)
        #pragma unroll
        for (int j = 0; j < 4; j++)
            #pragma unroll
            for (int q = 0; q < 4; q++) acc[i][j][q] = 0.f;

    prefetch(0, 0); CP_COMMIT();
    prefetch(1, 1); CP_COMMIT();

    for (int c = 0; c < nChunks; c++) {
        if (c + 1 < nChunks) CP_WAIT1(); else CP_WAIT0();
        __syncthreads();
        if (c + 2 < nChunks) { prefetch((c + 2) % 3, c + 2); CP_COMMIT(); }

        int buf = c % 3;
        uint32_t ahb = sb + (buf * 4 + 0) * MM_TELEM * 2;
        uint32_t alb = sb + (buf * 4 + 1) * MM_TELEM * 2;
        uint32_t bhb = sb + (buf * 4 + 2) * MM_TELEM * 2;
        uint32_t blb = sb + (buf * 4 + 3) * MM_TELEM * 2;

        #pragma unroll
        for (int kk = 0; kk < 32; kk += 16) {
            uint32_t ah[4][4], al[4][4], bh[2][4], bl[2][4];
            int arow = wm * 64 + (lane & 15);
            int acol = kk + ((lane >> 4) << 3);
            #pragma unroll
            for (int mt = 0; mt < 4; mt++) {
                uint32_t off = (uint32_t)(((arow + mt * 16) * MM_PITCH + acol) * 2);
                ldmx4(ah[mt], ahb + off);
                ldmx4(al[mt], alb + off);
            }
            int brow = wn * 32 + (lane & 7) + ((lane >> 4) & 1) * 8;
            int bcol = kk + ((lane >> 3) & 1) * 8;
            #pragma unroll
            for (int ng = 0; ng < 2; ng++) {
                uint32_t off = (uint32_t)(((brow + ng * 16) * MM_PITCH + bcol) * 2);
                ldmx4(bh[ng], bhb + off);
                ldmx4(bl[ng], blb + off);
            }
            #pragma unroll
            for (int mt = 0; mt < 4; mt++)
                #pragma unroll
                for (int nt = 0; nt < 4; nt++) {
                    const uint32_t* bhf = &bh[nt >> 1][(nt & 1) * 2];
                    const uint32_t* blf = &bl[nt >> 1][(nt & 1) * 2];
                    mma16816(acc[mt][nt], ah[mt], bhf);
                    mma16816(acc[mt][nt], ah[mt], blf);
                    mma16816(acc[mt][nt], al[mt], bhf);
                }
        }
    }

    int r0 = wm * 64 + (lane >> 2);
    int cc0 = wn * 32 + (lane & 3) * 2;
    if (mode < 2) {
        __nv_bfloat16* H = (mode == 0) ? g_Qh : g_Kh;
        __nv_bfloat16* L = (mode == 0) ? g_Ql : g_Kl;
        #pragma unroll
        for (int mt = 0; mt < 4; mt++) {
            size_t row1 = ((size_t)b * NPIX + n0 + r0 + mt * 16) * CDIM;
            size_t row2 = row1 + 8 * CDIM;
            #pragma unroll
            for (int nt = 0; nt < 4; nt++) {
                int o = o0 + cc0 + nt * 8;
                float b0 = bias[o], b1 = bias[o + 1];
                store_pair(H, L, row1 + o, acc[mt][nt][0] + b0, acc[mt][nt][1] + b1);
                store_pair(H, L, row2 + o, acc[mt][nt][2] + b0, acc[mt][nt][3] + b1);
            }
        }
    } else {
        #pragma unroll
        for (int mt = 0; mt < 4; mt++) {
            size_t row1 = ((size_t)b * NPIX + n0 + r0 + mt * 16) * CDIM;
            size_t row2 = row1 + 8 * CDIM;
            #pragma unroll
            for (int nt = 0; nt < 4; nt++) {
                int o = o0 + cc0 + nt * 8;
                float b0 = bias[o], b1 = bias[o + 1];
                *(float2*)(g_Vf + row1 + o) = make_float2(acc[mt][nt][0] + b0, acc[mt][nt][1] + b1);
                *(float2*)(g_Vf + row2 + o) = make_float2(acc[mt][nt][2] + b0, acc[mt][nt][3] + b1);
            }
        }
    }
}

// ---------------- 4) scores hh-only: HMMA 1-term, 3-stage pipeline ---------
__global__ void __launch_bounds__(256, 2) mm2hh_kernel() {
    extern __shared__ __align__(16) char smem2[];
    const int b  = blockIdx.z;
    const int n0 = blockIdx.x * 128;
    const int j0 = blockIdx.y * 128;

    const int pitch = CDIM, nChunks = CDIM / 32;
    const __nv_bfloat16* Ahp = g_Qh + ((size_t)b * NPIX + n0) * CDIM;
    const __nv_bfloat16* Bhp = g_Kh + ((size_t)b * NPIX + j0) * CDIM;
    __nv_bfloat16* outp = g_Sh + (size_t)b * NPIX * NPIX + (size_t)n0 * NPIX + j0;

    const uint32_t sb = smem_to_u32(smem2);
    const int tid = threadIdx.x;
    const int lane = tid & 31, wid = tid >> 5;
    const int wm = wid >> 2, wn = wid & 3;

    const __nv_bfloat16* ptrs[2] = {Ahp, Bhp};
    auto prefetch = [&](int buf, int c) {
        int col0 = c * 32;
        #pragma unroll
        for (int t2 = 0; t2 < 2; t2++) {
            #pragma unroll
            for (int s = 0; s < 2; s++) {
                int sidx = tid + s * 256;
                int row = sidx >> 2, cs = (sidx & 3) * 8;
                const void* g = ptrs[t2] + (size_t)row * pitch + col0 + cs;
                uint32_t sa = sb + (uint32_t)((((buf * 2 + t2) * MM_TELEM) + row * MM_PITCH + cs) * 2);
                cpasync16(sa, g);
            }
        }
    };

    float acc[4][4][4];
    #pragma unroll
    for (int i = 0; i < 4; i++)
        #pragma unroll
        for (int j = 0; j < 4; j++)
            #pragma unroll
            for (int q = 0; q < 4; q++) acc[i][j][q] = 0.f;

    prefetch(0, 0); CP_COMMIT();
    prefetch(1, 1); CP_COMMIT();

    for (int c = 0; c < nChunks; c++) {
        if (c + 1 < nChunks) CP_WAIT1(); else CP_WAIT0();
        __syncthreads();
        if (c + 2 < nChunks) { prefetch((c + 2) % 3, c + 2); CP_COMMIT(); }

        int buf = c % 3;
        uint32_t ahb = sb + (buf * 2 + 0) * MM_TELEM * 2;
        uint32_t bhb = sb + (buf * 2 + 1) * MM_TELEM * 2;

        #pragma unroll
        for (int kk = 0; kk < 32; kk += 16) {
            uint32_t ah[4][4], bh[2][4];
            int arow = wm * 64 + (lane & 15);
            int acol = kk + ((lane >> 4) << 3);
            #pragma unroll
            for (int mt = 0; mt < 4; mt++) {
                uint32_t off = (uint32_t)(((arow + mt * 16) * MM_PITCH + acol) * 2);
                ldmx4(ah[mt], ahb + off);
            }
            int brow = wn * 32 + (lane & 7) + ((lane >> 4) & 1) * 8;
            int bcol = kk + ((lane >> 3) & 1) * 8;
            #pragma unroll
            for (int ng = 0; ng < 2; ng++) {
                uint32_t off = (uint32_t)(((brow + ng * 16) * MM_PITCH + bcol) * 2);
                ldmx4(bh[ng], bhb + off);
            }
            #pragma unroll
            for (int mt = 0; mt < 4; mt++)
                #pragma unroll
                for (int nt = 0; nt < 4; nt++)
                    mma16816(acc[mt][nt], ah[mt], &bh[nt >> 1][(nt & 1) * 2]);
        }
    }

    int r0 = wm * 64 + (lane >> 2);
    int c0 = wn * 32 + (lane & 3) * 2;
    #pragma unroll
    for (int mt = 0; mt < 4; mt++)
        #pragma unroll
        for (int nt = 0; nt < 4; nt++) {
            __nv_bfloat162 p01, p23;
            p01.x = __float2bfloat16(acc[mt][nt][0]);
            p01.y = __float2bfloat16(acc[mt][nt][1]);
            p23.x = __float2bfloat16(acc[mt][nt][2]);
            p23.y = __float2bfloat16(acc[mt][nt][3]);
            *(__nv_bfloat162*)(outp + (size_t)(r0 + mt * 16) * NPIX + c0 + nt * 8)     = p01;
            *(__nv_bfloat162*)(outp + (size_t)(r0 + mt * 16 + 8) * NPIX + c0 + nt * 8) = p23;
        }
}

// ---------------- 5) fused: select + rescore + softmax + PV + epilogue -----
__global__ void __launch_bounds__(256) attn_fused_kernel(const float* __restrict__ F_c,
                                                         float* __restrict__ out) {
    __shared__ float qs[CDIM];
    __shared__ int   s_idx[256];
    __shared__ int   s_kidx[256];
    __shared__ float s_val[256];
    __shared__ int   wtot[8];
    __shared__ float sh[8];
    __shared__ float f_b;
    __shared__ int   i_b;

    int r = blockIdx.x;
    int b = r >> 12, n = r & (NPIX - 1);
    int tid = threadIdx.x, lane = tid & 31, w = tid >> 5;

    // --- load this thread's 16 approx scores ---
    const __nv_bfloat16* srow = g_Sh + (size_t)r * NPIX;
    float ls[16];
    {
        uint4 u0 = *(const uint4*)(srow + tid * 16);
        uint4 u1 = *(const uint4*)(srow + tid * 16 + 8);
        const __nv_bfloat16* p0 = (const __nv_bfloat16*)&u0;
        const __nv_bfloat16* p1 = (const __nv_bfloat16*)&u1;
        #pragma unroll
        for (int j = 0; j < 8; j++) { ls[j] = __bfloat162float(p0[j]); ls[8 + j] = __bfloat162float(p1[j]); }
    }
    // --- approx row max ---
    float mx = -1e30f;
    #pragma unroll
    for (int j = 0; j < 16; j++) mx = fmaxf(mx, ls[j]);
    mx = warpMax(mx);
    if (lane == 0) sh[w] = mx;
    __syncthreads();
    if (w == 0) {
        mx = (lane < 8) ? sh[lane] : -1e30f;
        mx = warpMax(mx);
        if (lane == 0) f_b = mx;
    }
    __syncthreads();
    float thr = f_b - SEL_TH;

    // --- select candidates (warp-scan compaction, deterministic) ---
    int c = 0;
    #pragma unroll
    for (int j = 0; j < 16; j++) if (ls[j] >= thr) c++;
    int incl = warpInclScan(c, lane);
    if (lane == 31) wtot[w] = incl;
    __syncthreads();
    if (w == 0 && lane < 8) {
        int t = wtot[lane];
        #pragma unroll
        for (int o2 = 1; o2 < 8; o2 <<= 1) {
            int u = __shfl_up_sync(0xffu, t, o2);
            if (lane >= o2) t += u;
        }
        wtot[lane] = t;
    }
    __syncthreads();
    int base0 = (w > 0) ? wtot[w - 1] : 0;
    int end = base0 + incl, start = end - c;
    int cnt = wtot[7]; if (cnt > 256) cnt = 256;
    int o = start;
    #pragma unroll
    for (int j = 0; j < 16; j++) {
        if (ls[j] >= thr && o < 256) s_idx[o++] = tid * 16 + j;
    }

    // --- q row (fp32 = hi+lo) ---
    {
        const __nv_bfloat16* qh = g_Qh + ((size_t)(b * NPIX + n)) * CDIM;
        const __nv_bfloat16* ql = g_Ql + ((size_t)(b * NPIX + n)) * CDIM;
        __nv_bfloat162 a = *(const __nv_bfloat162*)(qh + tid * 2);
        __nv_bfloat162 d = *(const __nv_bfloat162*)(ql + tid * 2);
        qs[tid * 2]     = __bfloat162float(a.x) + __bfloat162float(d.x);
        qs[tid * 2 + 1] = __bfloat162float(a.y) + __bfloat162float(d.y);
    }
    __syncthreads();

    // --- exact rescore: warp per candidate ---
    for (int ci = w; ci < cnt; ci += 8) {
        int m = s_idx[ci];
        const __nv_bfloat16* kh = g_Kh + ((size_t)(b * NPIX + m)) * CDIM + lane * 16;
        const __nv_bfloat16* kl = g_Kl + ((size_t)(b * NPIX + m)) * CDIM + lane * 16;
        uint4 h0 = *(const uint4*)(kh);
        uint4 h1 = *(const uint4*)(kh + 8);
        uint4 l0 = *(const uint4*)(kl);
        uint4 l1 = *(const uint4*)(kl + 8);
        const __nv_bfloat16* ph0 = (const __nv_bfloat16*)&h0;
        const __nv_bfloat16* ph1 = (const __nv_bfloat16*)&h1;
        const __nv_bfloat16* pl0 = (const __nv_bfloat16*)&l0;
        const __nv_bfloat16* pl1 = (const __nv_bfloat16*)&l1;
        float d = 0.f;
        #pragma unroll
        for (int j = 0; j < 8; j++) {
            d = fmaf(qs[lane * 16 + j],     __bfloat162float(ph0[j]) + __bfloat162float(pl0[j]), d);
            d = fmaf(qs[lane * 16 + 8 + j], __bfloat162float(ph1[j]) + __bfloat162float(pl1[j]), d);
        }
        d = warpSum(d);
        if (lane == 0) s_val[ci] = d;
    }
    __syncthreads();

    // --- exact max over candidates ---
    float lm = (tid < cnt) ? s_val[tid] : -1e30f;
    lm = warpMax(lm);
    if (lane == 0) sh[w] = lm;
    __syncthreads();
    if (w == 0) {
        lm = (lane < 8) ? sh[lane] : -1e30f;
        lm = warpMax(lm);
        if (lane == 0) f_b = lm;
    }
    __syncthreads();
    float emax = f_b;

    // --- exp + Z (deterministic) ---
    float e = (tid < cnt) ? __expf(s_val[tid] - emax) : 0.f;
    float ps = warpSum(e);
    __syncthreads();
    if (lane == 0) sh[w] = ps;
    __syncthreads();
    if (w == 0) {
        ps = (lane < 8) ? sh[lane] : 0.f;
        ps = warpSum(ps);
        if (lane == 0) f_b = ps;
    }
    __syncthreads();
    float Z = f_b;
    float invZ = 1.f / Z;

    // --- compact kept list (weight >= PVW), warp-scan ---
    int k = (tid < cnt && e >= PVW * Z) ? 1 : 0;
    int incl2 = warpInclScan(k, lane);
    if (lane == 31) wtot[w] = incl2;
    __syncthreads();
    if (w == 0 && lane < 8) {
        int t = wtot[lane];
        #pragma unroll
        for (int o2 = 1; o2 < 8; o2 <<= 1) {
            int u = __shfl_up_sync(0xffu, t, o2);
            if (lane >= o2) t += u;
        }
        wtot[lane] = t;
    }
    __syncthreads();
    if (k) {
        int pos = ((w > 0) ? wtot[w - 1] : 0) + incl2 - 1;
        s_kidx[pos] = s_idx[tid];
        s_val[pos]  = e * invZ;
    }
    __syncthreads();
    int nk = wtot[7];

    // --- sparse PV (V^2 on the fly) + fused epilogue ---
    int ch = tid * 2;
    float2 macc  = make_float2(0.f, 0.f);
    float2 m2acc = make_float2(0.f, 0.f);
    for (int e2 = 0; e2 < nk; e2++) {
        int m = s_kidx[e2];
        float ww = s_val[e2];
        size_t vb = ((size_t)(b * NPIX + m)) * CDIM + ch;
        float2 v = *(const float2*)(g_Vf + vb);
        macc.x  = fmaf(ww, v.x,       macc.x);  macc.y  = fmaf(ww, v.y,       macc.y);
        m2acc.x = fmaf(ww, v.x * v.x, m2acc.x); m2acc.y = fmaf(ww, v.y * v.y, m2acc.y);
    }
    // epilogue: out[b][ch][n] = sqrt(clip(M2-M^2)+eps) * (F_c - mean)*inv + M
    {
        float s0 = sqrtf(fmaxf(m2acc.x - macc.x * macc.x, 0.f) + 1e-8f);
        float s1 = sqrtf(fmaxf(m2acc.y - macc.y * macc.y, 0.f) + 1e-8f);
        size_t f0 = ((size_t)(b * CDIM + ch)) * NPIX + n;
        size_t f1 = f0 + NPIX;
        float fn0 = (F_c[f0] - g_mean[2][ch])     * g_inv[2][ch];
        float fn1 = (F_c[f1] - g_mean[2][ch + 1]) * g_inv[2][ch + 1];
        out[f0] = s0 * fn0 + macc.x;
        out[f1] = s1 * fn1 + macc.y;
    }
}

// ---------------- launch ----------------
extern "C" void kernel_launch(void* const* d_in, const int* in_sizes, int n_in,
                              void* d_out, int out_size) {
    const float* F_c      = (const float*)d_in[0];
    const float* F_s      = (const float*)d_in[1];
    const float* F_c_prev = (const float*)d_in[2];
    const float* F_s_prev = (const float*)d_in[3];
    const float* Wf = (const float*)d_in[4];
    const float* bf = (const float*)d_in[5];
    const float* Wg = (const float*)d_in[6];
    const float* bg = (const float*)d_in[7];
    const float* Wh = (const float*)d_in[8];
    const float* bh = (const float*)d_in[9];
    float* out = (float*)d_out;

    cudaFuncSetAttribute(mm2hh_kernel, cudaFuncAttributeMaxDynamicSharedMemorySize, MM_SMEM2);
    cudaFuncSetAttribute(projmma3_kernel, cudaFuncAttributeMaxDynamicSharedMemorySize, MM_SMEM4);

    stats_kernel<<<dim3(CDIM, 3), 256>>>(F_c_prev, F_s_prev, F_c);
    fold_kernel<<<dim3(CDIM, 3), 256>>>(Wf, bf, Wg, bg, Wh, bh);

    transpose_split_kernel<<<dim3(NPIX / 32, CDIM / 32, 12), dim3(32, 8)>>>(
        F_c_prev, F_s_prev, F_s);

    projmma3_kernel<<<dim3(NPIX / 128, CDIM / 128, 12), 256, MM_SMEM4>>>();

    mm2hh_kernel<<<dim3(NPIX / 128, NPIX / 128, BATCH), 256, MM_SMEM2>>>();
    attn_fused_kernel<<<BATCH * NPIX, 256>>>(F_c, out);
}

// round 12
// speedup vs baseline: 1.0450x; 1.0450x over previous
#include <cuda_runtime.h>
#include <cuda_bf16.h>
#include <math.h>
#include <stdint.h>

#define BATCH 4
#define CDIM  512
#define NPIX  4096
#define NPC   (BATCH * NPIX)
#define SEL_TH 13.8f          // candidate selection window below approx max
#define PVW    2e-6f          // PV weight prune threshold

// ---------------- scratch (device globals; device-code access ONLY) --------
__device__ float g_mean[3][CDIM];
__device__ float g_inv[3][CDIM];
__device__ float g_b3[3][CDIM];                                      // biases (folded f,g; raw h)
__device__ __align__(256) __nv_bfloat16 g_Wh3[3][CDIM * CDIM];       // weights hi
__device__ __align__(256) __nv_bfloat16 g_Wl3[3][CDIM * CDIM];       // weights lo
__device__ __align__(256) __nv_bfloat16 g_Xh[(size_t)3 * BATCH * NPIX * CDIM];  // inputs [t][b][n][c] hi
__device__ __align__(256) __nv_bfloat16 g_Xl[(size_t)3 * BATCH * NPIX * CDIM];  // inputs lo
__device__ __align__(256) __nv_bfloat16 g_Qh[(size_t)BATCH * NPIX * CDIM];   // [b][n][c]
__device__ __align__(256) __nv_bfloat16 g_Ql[(size_t)BATCH * NPIX * CDIM];
__device__ __align__(256) __nv_bfloat16 g_Kh[(size_t)BATCH * NPIX * CDIM];
__device__ __align__(256) __nv_bfloat16 g_Kl[(size_t)BATCH * NPIX * CDIM];
__device__ float g_Vf[(size_t)BATCH * NPIX * CDIM];    // V [b][m][v] fp32
__device__ __align__(256) __nv_bfloat16 g_Sh[(size_t)BATCH * NPIX * NPIX];  // hh scores bf16
__device__ float g_M[(size_t)BATCH * NPIX * CDIM];     // [b][n][v]
__device__ float g_M2[(size_t)BATCH * NPIX * CDIM];

// ---------------- PTX helpers (baseline sm_80+ instructions only) ----------
__device__ __forceinline__ uint32_t smem_to_u32(const void* p) {
    uint32_t a;
    asm("{ .reg .u64 t; cvta.to.shared.u64 t, %1; cvt.u32.u64 %0, t; }" : "=r"(a) : "l"(p));
    return a;
}
__device__ __forceinline__ void ldmx4(uint32_t* r, uint32_t addr) {
    asm volatile("ldmatrix.sync.aligned.m8n8.x4.shared.b16 {%0,%1,%2,%3}, [%4];"
                 : "=r"(r[0]), "=r"(r[1]), "=r"(r[2]), "=r"(r[3]) : "r"(addr));
}
__device__ __forceinline__ void mma16816(float* c, const uint32_t* a, const uint32_t* b) {
    asm volatile("mma.sync.aligned.m16n8k16.row.col.f32.bf16.bf16.f32 "
                 "{%0,%1,%2,%3},{%4,%5,%6,%7},{%8,%9},{%0,%1,%2,%3};"
                 : "+f"(c[0]), "+f"(c[1]), "+f"(c[2]), "+f"(c[3])
                 : "r"(a[0]), "r"(a[1]), "r"(a[2]), "r"(a[3]), "r"(b[0]), "r"(b[1]));
}
__device__ __forceinline__ void cpasync16(uint32_t saddr, const void* g) {
    asm volatile("cp.async.cg.shared.global [%0], [%1], 16;" :: "r"(saddr), "l"(g));
}
#define CP_COMMIT() asm volatile("cp.async.commit_group;" ::: "memory")
#define CP_WAIT1()  asm volatile("cp.async.wait_group 1;" ::: "memory")
#define CP_WAIT0()  asm volatile("cp.async.wait_group 0;" ::: "memory")

// ---------------- reductions / split ----------------
__device__ __forceinline__ float warpSum(float v) {
    #pragma unroll
    for (int o = 16; o; o >>= 1) v += __shfl_down_sync(0xffffffffu, v, o);
    return v;
}
__device__ __forceinline__ float warpMax(float v) {
    #pragma unroll
    for (int o = 16; o; o >>= 1) v = fmaxf(v, __shfl_down_sync(0xffffffffu, v, o));
    return v;
}
__device__ __forceinline__ int warpInclScan(int v, int lane) {
    #pragma unroll
    for (int o = 1; o < 32; o <<= 1) {
        int t = __shfl_up_sync(0xffffffffu, v, o);
        if (lane >= o) v += t;
    }
    return v;
}
__device__ __forceinline__ void split2(float v, __nv_bfloat16& h, __nv_bfloat16& l) {
    h = __float2bfloat16(v);
    l = __float2bfloat16(v - __bfloat162float(h));
}
__device__ __forceinline__ void store_pair(__nv_bfloat16* H, __nv_bfloat16* L,
                                           size_t idx, float a, float b) {
    __nv_bfloat16 h0, l0, h1, l1;
    split2(a, h0, l0); split2(b, h1, l1);
    __nv_bfloat162 hh; hh.x = h0; hh.y = h1;
    __nv_bfloat162 ll; ll.x = l0; ll.y = l1;
    *(__nv_bfloat162*)(H + idx) = hh;
    *(__nv_bfloat162*)(L + idx) = ll;
}

// ---------------- 1) channel stats ----------------
__global__ void stats_kernel(const float* __restrict__ x0,
                             const float* __restrict__ x1,
                             const float* __restrict__ x2) {
    int c = blockIdx.x, t = blockIdx.y;
    const float* x = (t == 0) ? x0 : (t == 1 ? x1 : x2);
    float s = 0.f, ss = 0.f;
    for (int b = 0; b < BATCH; b++) {
        const float* p = x + ((size_t)b * CDIM + c) * NPIX;
        for (int i = threadIdx.x * 4; i < NPIX; i += blockDim.x * 4) {
            float4 v = *(const float4*)(p + i);
            s  += v.x + v.y + v.z + v.w;
            ss += v.x * v.x + v.y * v.y + v.z * v.z + v.w * v.w;
        }
    }
    __shared__ float sh1[8], sh2[8];
    int lane = threadIdx.x & 31, w = threadIdx.x >> 5;
    s = warpSum(s); ss = warpSum(ss);
    if (lane == 0) { sh1[w] = s; sh2[w] = ss; }
    __syncthreads();
    if (w == 0) {
        s  = (lane < (blockDim.x >> 5)) ? sh1[lane] : 0.f;
        ss = (lane < (blockDim.x >> 5)) ? sh2[lane] : 0.f;
        s = warpSum(s); ss = warpSum(ss);
        if (lane == 0) {
            float mean = s / (float)NPC;
            float var  = fmaxf(ss - s * mean, 0.f) / (float)(NPC - 1);
            g_mean[t][c] = mean;
            g_inv[t][c]  = 1.f / (sqrtf(var) + 1e-12f);
        }
    }
}

// ---------------- 2) fold norm into weights, emit bf16 hi/lo ---------------
__global__ void fold_kernel(const float* __restrict__ Wf, const float* __restrict__ bf,
                            const float* __restrict__ Wg, const float* __restrict__ bg,
                            const float* __restrict__ Wh, const float* __restrict__ bh) {
    int o = blockIdx.x, t = blockIdx.y;
    const float* W  = (t == 0) ? Wf : (t == 1) ? Wg : Wh;
    const float* bb = (t == 0) ? bf : (t == 1) ? bg : bh;
    float acc = 0.f;
    for (int c = threadIdx.x; c < CDIM; c += blockDim.x) {
        float w = W[(size_t)o * CDIM + c];
        if (t < 2) w *= g_inv[t][c];
        __nv_bfloat16 h, l;
        split2(w, h, l);
        g_Wh3[t][(size_t)o * CDIM + c] = h;
        g_Wl3[t][(size_t)o * CDIM + c] = l;
        if (t < 2) acc += w * g_mean[t][c];
    }
    if (t == 2) {
        if (threadIdx.x == 0) g_b3[2][o] = bb[o];
        return;
    }
    __shared__ float sh[8];
    int lane = threadIdx.x & 31, w2 = threadIdx.x >> 5;
    acc = warpSum(acc);
    if (lane == 0) sh[w2] = acc;
    __syncthreads();
    if (w2 == 0) {
        acc = (lane < (blockDim.x >> 5)) ? sh[lane] : 0.f;
        acc = warpSum(acc);
        if (lane == 0) g_b3[t][o] = bb[o] - acc;
    }
}

// ---------------- 3a) transpose+split inputs: [b][c][n] f32 -> [t][b][n][c] bf16 hi/lo
__global__ void transpose_split_kernel(const float* __restrict__ x0,
                                       const float* __restrict__ x1,
                                       const float* __restrict__ x2) {
    __shared__ float tile[32][33];
    int z = blockIdx.z;
    int t = z >> 2, b = z & 3;
    const float* X = (t == 0) ? x0 : (t == 1) ? x1 : x2;
    int n0 = blockIdx.x * 32, c0 = blockIdx.y * 32;
    int tx = threadIdx.x, ty = threadIdx.y;
    #pragma unroll
    for (int i = 0; i < 4; i++)
        tile[ty + i * 8][tx] = X[((size_t)b * CDIM + c0 + ty + i * 8) * NPIX + n0 + tx];
    __syncthreads();
    #pragma unroll
    for (int i = 0; i < 4; i++) {
        float v = tile[tx][ty + i * 8];
        __nv_bfloat16 h, l;
        split2(v, h, l);
        size_t idx = (((size_t)(t * BATCH + b)) * NPIX + n0 + ty + i * 8) * CDIM + c0 + tx;
        g_Xh[idx] = h;
        g_Xl[idx] = l;
    }
}

// ---------------- shared tile constants ------------------------------------
#define MM_PITCH 40
#define MM_TELEM (128 * MM_PITCH)
#define MM_SMEM4 (3 * 4 * MM_TELEM * 2)    // 122880 bytes (4 tiles, 3 buf)
#define MM_SMEM2 (3 * 2 * MM_TELEM * 2)    // 61440 bytes  (2 tiles, 3 buf)

// ---------------- 3b) projection GEMM, 3-stage cp.async pipeline -----------
__global__ void __launch_bounds__(256, 1) projmma3_kernel() {
    extern __shared__ __align__(16) char smem2[];
    const int z = blockIdx.z;
    const int mode = z >> 2, b = z & 3;
    const int n0 = blockIdx.x * 128;
    const int o0 = blockIdx.y * 128;

    const int pitch = CDIM, nChunks = CDIM / 32;
    const __nv_bfloat16* Ahp = g_Xh + (((size_t)(mode * BATCH + b)) * NPIX + n0) * CDIM;
    const __nv_bfloat16* Alp = g_Xl + (((size_t)(mode * BATCH + b)) * NPIX + n0) * CDIM;
    const __nv_bfloat16* Bhp = g_Wh3[mode] + (size_t)o0 * CDIM;
    const __nv_bfloat16* Blp = g_Wl3[mode] + (size_t)o0 * CDIM;
    const float* bias = g_b3[mode];

    const uint32_t sb = smem_to_u32(smem2);
    const int tid = threadIdx.x;
    const int lane = tid & 31, wid = tid >> 5;
    const int wm = wid >> 2, wn = wid & 3;

    const __nv_bfloat16* ptrs[4] = {Ahp, Alp, Bhp, Blp};
    auto prefetch = [&](int buf, int c) {
        int col0 = c * 32;
        #pragma unroll
        for (int t4 = 0; t4 < 4; t4++) {
            #pragma unroll
            for (int s = 0; s < 2; s++) {
                int sidx = tid + s * 256;
                int row = sidx >> 2, cs = (sidx & 3) * 8;
                const void* g = ptrs[t4] + (size_t)row * pitch + col0 + cs;
                uint32_t sa = sb + (uint32_t)((((buf * 4 + t4) * MM_TELEM) + row * MM_PITCH + cs) * 2);
                cpasync16(sa, g);
            }
        }
    };

    float acc[4][4][4];
    #pragma unroll
    for (int i = 0; i < 4; i++)
        #pragma unroll
        for (int j = 0; j < 4; j++)
            #pragma unroll
            for (int q = 0; q < 4; q++) acc[i][j][q] = 0.f;

    prefetch(0, 0); CP_COMMIT();
    prefetch(1, 1); CP_COMMIT();

    for (int c = 0; c < nChunks; c++) {
        if (c + 1 < nChunks) CP_WAIT1(); else CP_WAIT0();
        __syncthreads();
        if (c + 2 < nChunks) { prefetch((c + 2) % 3, c + 2); CP_COMMIT(); }

        int buf = c % 3;
        uint32_t ahb = sb + (buf * 4 + 0) * MM_TELEM * 2;
        uint32_t alb = sb + (buf * 4 + 1) * MM_TELEM * 2;
        uint32_t bhb = sb + (buf * 4 + 2) * MM_TELEM * 2;
        uint32_t blb = sb + (buf * 4 + 3) * MM_TELEM * 2;

        #pragma unroll
        for (int kk = 0; kk < 32; kk += 16) {
            uint32_t ah[4][4], al[4][4], bh[2][4], bl[2][4];
            int arow = wm * 64 + (lane & 15);
            int acol = kk + ((lane >> 4) << 3);
            #pragma unroll
            for (int mt = 0; mt < 4; mt++) {
                uint32_t off = (uint32_t)(((arow + mt * 16) * MM_PITCH + acol) * 2);
                ldmx4(ah[mt], ahb + off);
                ldmx4(al[mt], alb + off);
            }
            int brow = wn * 32 + (lane & 7) + ((lane >> 4) & 1) * 8;
            int bcol = kk + ((lane >> 3) & 1) * 8;
            #pragma unroll
            for (int ng = 0; ng < 2; ng++) {
                uint32_t off = (uint32_t)(((brow + ng * 16) * MM_PITCH + bcol) * 2);
                ldmx4(bh[ng], bhb + off);
                ldmx4(bl[ng], blb + off);
            }
            #pragma unroll
            for (int mt = 0; mt < 4; mt++)
                #pragma unroll
                for (int nt = 0; nt < 4; nt++) {
                    const uint32_t* bhf = &bh[nt >> 1][(nt & 1) * 2];
                    const uint32_t* blf = &bl[nt >> 1][(nt & 1) * 2];
                    mma16816(acc[mt][nt], ah[mt], bhf);
                    mma16816(acc[mt][nt], ah[mt], blf);
                    mma16816(acc[mt][nt], al[mt], bhf);
                }
        }
    }

    int r0 = wm * 64 + (lane >> 2);
    int cc0 = wn * 32 + (lane & 3) * 2;
    if (mode < 2) {
        __nv_bfloat16* H = (mode == 0) ? g_Qh : g_Kh;
        __nv_bfloat16* L = (mode == 0) ? g_Ql : g_Kl;
        #pragma unroll
        for (int mt = 0; mt < 4; mt++) {
            size_t row1 = ((size_t)b * NPIX + n0 + r0 + mt * 16) * CDIM;
            size_t row2 = row1 + 8 * CDIM;
            #pragma unroll
            for (int nt = 0; nt < 4; nt++) {
                int o = o0 + cc0 + nt * 8;
                float b0 = bias[o], b1 = bias[o + 1];
                store_pair(H, L, row1 + o, acc[mt][nt][0] + b0, acc[mt][nt][1] + b1);
                store_pair(H, L, row2 + o, acc[mt][nt][2] + b0, acc[mt][nt][3] + b1);
            }
        }
    } else {
        #pragma unroll
        for (int mt = 0; mt < 4; mt++) {
            size_t row1 = ((size_t)b * NPIX + n0 + r0 + mt * 16) * CDIM;
            size_t row2 = row1 + 8 * CDIM;
            #pragma unroll
            for (int nt = 0; nt < 4; nt++) {
                int o = o0 + cc0 + nt * 8;
                float b0 = bias[o], b1 = bias[o + 1];
                *(float2*)(g_Vf + row1 + o) = make_float2(acc[mt][nt][0] + b0, acc[mt][nt][1] + b1);
                *(float2*)(g_Vf + row2 + o) = make_float2(acc[mt][nt][2] + b0, acc[mt][nt][3] + b1);
            }
        }
    }
}

// ---------------- 4) scores hh-only: HMMA 1-term, 3-stage pipeline ---------
__global__ void __launch_bounds__(256, 2) mm2hh_kernel() {
    extern __shared__ __align__(16) char smem2[];
    const int b  = blockIdx.z;
    const int n0 = blockIdx.x * 128;
    const int j0 = blockIdx.y * 128;

    const int pitch = CDIM, nChunks = CDIM / 32;
    const __nv_bfloat16* Ahp = g_Qh + ((size_t)b * NPIX + n0) * CDIM;
    const __nv_bfloat16* Bhp = g_Kh + ((size_t)b * NPIX + j0) * CDIM;
    __nv_bfloat16* outp = g_Sh + (size_t)b * NPIX * NPIX + (size_t)n0 * NPIX + j0;

    const uint32_t sb = smem_to_u32(smem2);
    const int tid = threadIdx.x;
    const int lane = tid & 31, wid = tid >> 5;
    const int wm = wid >> 2, wn = wid & 3;

    const __nv_bfloat16* ptrs[2] = {Ahp, Bhp};
    auto prefetch = [&](int buf, int c) {
        int col0 = c * 32;
        #pragma unroll
        for (int t2 = 0; t2 < 2; t2++) {
            #pragma unroll
            for (int s = 0; s < 2; s++) {
                int sidx = tid + s * 256;
                int row = sidx >> 2, cs = (sidx & 3) * 8;
                const void* g = ptrs[t2] + (size_t)row * pitch + col0 + cs;
                uint32_t sa = sb + (uint32_t)((((buf * 2 + t2) * MM_TELEM) + row * MM_PITCH + cs) * 2);
                cpasync16(sa, g);
            }
        }
    };

    float acc[4][4][4];
    #pragma unroll
    for (int i = 0; i < 4; i++)
        #pragma unroll
        for (int j = 0; j < 4; j++)
            #pragma unroll
            for (int q = 0; q < 4; q++) acc[i][j][q] = 0.f;

    prefetch(0, 0); CP_COMMIT();
    prefetch(1, 1); CP_COMMIT();

    for (int c = 0; c < nChunks; c++) {
        if (c + 1 < nChunks) CP_WAIT1(); else CP_WAIT0();
        __syncthreads();
        if (c + 2 < nChunks) { prefetch((c + 2) % 3, c + 2); CP_COMMIT(); }

        int buf = c % 3;
        uint32_t ahb = sb + (buf * 2 + 0) * MM_TELEM * 2;
        uint32_t bhb = sb + (buf * 2 + 1) * MM_TELEM * 2;

        #pragma unroll
        for (int kk = 0; kk < 32; kk += 16) {
            uint32_t ah[4][4], bh[2][4];
            int arow = wm * 64 + (lane & 15);
            int acol = kk + ((lane >> 4) << 3);
            #pragma unroll
            for (int mt = 0; mt < 4; mt++) {
                uint32_t off = (uint32_t)(((arow + mt * 16) * MM_PITCH + acol) * 2);
                ldmx4(ah[mt], ahb + off);
            }
            int brow = wn * 32 + (lane & 7) + ((lane >> 4) & 1) * 8;
            int bcol = kk + ((lane >> 3) & 1) * 8;
            #pragma unroll
            for (int ng = 0; ng < 2; ng++) {
                uint32_t off = (uint32_t)(((brow + ng * 16) * MM_PITCH + bcol) * 2);
                ldmx4(bh[ng], bhb + off);
            }
            #pragma unroll
            for (int mt = 0; mt < 4; mt++)
                #pragma unroll
                for (int nt = 0; nt < 4; nt++)
                    mma16816(acc[mt][nt], ah[mt], &bh[nt >> 1][(nt & 1) * 2]);
        }
    }

    int r0 = wm * 64 + (lane >> 2);
    int c0 = wn * 32 + (lane & 3) * 2;
    #pragma unroll
    for (int mt = 0; mt < 4; mt++)
        #pragma unroll
        for (int nt = 0; nt < 4; nt++) {
            __nv_bfloat162 p01, p23;
            p01.x = __float2bfloat16(acc[mt][nt][0]);
            p01.y = __float2bfloat16(acc[mt][nt][1]);
            p23.x = __float2bfloat16(acc[mt][nt][2]);
            p23.y = __float2bfloat16(acc[mt][nt][3]);
            *(__nv_bfloat162*)(outp + (size_t)(r0 + mt * 16) * NPIX + c0 + nt * 8)     = p01;
            *(__nv_bfloat162*)(outp + (size_t)(r0 + mt * 16 + 8) * NPIX + c0 + nt * 8) = p23;
        }
}

// ---------------- 5) fused: select + exact rescore + softmax + sparse PV ---
__global__ void __launch_bounds__(256) attn_fused_kernel() {
    __shared__ float qs[CDIM];
    __shared__ int   s_idx[256];
    __shared__ int   s_kidx[256];
    __shared__ float s_val[256];
    __shared__ int   wtot[8];
    __shared__ float sh[8];
    __shared__ float f_b;

    int r = blockIdx.x;
    int b = r >> 12, n = r & (NPIX - 1);
    int tid = threadIdx.x, lane = tid & 31, w = tid >> 5;

    // --- load this thread's 16 approx scores ---
    const __nv_bfloat16* srow = g_Sh + (size_t)r * NPIX;
    float ls[16];
    {
        uint4 u0 = *(const uint4*)(srow + tid * 16);
        uint4 u1 = *(const uint4*)(srow + tid * 16 + 8);
        const __nv_bfloat16* p0 = (const __nv_bfloat16*)&u0;
        const __nv_bfloat16* p1 = (const __nv_bfloat16*)&u1;
        #pragma unroll
        for (int j = 0; j < 8; j++) { ls[j] = __bfloat162float(p0[j]); ls[8 + j] = __bfloat162float(p1[j]); }
    }
    // --- approx row max ---
    float mx = -1e30f;
    #pragma unroll
    for (int j = 0; j < 16; j++) mx = fmaxf(mx, ls[j]);
    mx = warpMax(mx);
    if (lane == 0) sh[w] = mx;
    __syncthreads();
    if (w == 0) {
        mx = (lane < 8) ? sh[lane] : -1e30f;
        mx = warpMax(mx);
        if (lane == 0) f_b = mx;
    }
    __syncthreads();
    float thr = f_b - SEL_TH;

    // --- select candidates (warp-scan compaction, deterministic) ---
    int c = 0;
    #pragma unroll
    for (int j = 0; j < 16; j++) if (ls[j] >= thr) c++;
    int incl = warpInclScan(c, lane);
    if (lane == 31) wtot[w] = incl;
    __syncthreads();
    if (w == 0 && lane < 8) {
        int t = wtot[lane];
        #pragma unroll
        for (int o2 = 1; o2 < 8; o2 <<= 1) {
            int u = __shfl_up_sync(0xffu, t, o2);
            if (lane >= o2) t += u;
        }
        wtot[lane] = t;
    }
    __syncthreads();
    int base0 = (w > 0) ? wtot[w - 1] : 0;
    int end = base0 + incl, start = end - c;
    int cnt = wtot[7]; if (cnt > 256) cnt = 256;
    int o = start;
    #pragma unroll
    for (int j = 0; j < 16; j++) {
        if (ls[j] >= thr && o < 256) s_idx[o++] = tid * 16 + j;
    }

    // --- q row (fp32 = hi+lo) ---
    {
        const __nv_bfloat16* qh = g_Qh + ((size_t)(b * NPIX + n)) * CDIM;
        const __nv_bfloat16* ql = g_Ql + ((size_t)(b * NPIX + n)) * CDIM;
        __nv_bfloat162 a = *(const __nv_bfloat162*)(qh + tid * 2);
        __nv_bfloat162 d = *(const __nv_bfloat162*)(ql + tid * 2);
        qs[tid * 2]     = __bfloat162float(a.x) + __bfloat162float(d.x);
        qs[tid * 2 + 1] = __bfloat162float(a.y) + __bfloat162float(d.y);
    }
    __syncthreads();

    // --- exact rescore: warp per candidate ---
    for (int ci = w; ci < cnt; ci += 8) {
        int m = s_idx[ci];
        const __nv_bfloat16* kh = g_Kh + ((size_t)(b * NPIX + m)) * CDIM + lane * 16;
        const __nv_bfloat16* kl = g_Kl + ((size_t)(b * NPIX + m)) * CDIM + lane * 16;
        uint4 h0 = *(const uint4*)(kh);
        uint4 h1 = *(const uint4*)(kh + 8);
        uint4 l0 = *(const uint4*)(kl);
        uint4 l1 = *(const uint4*)(kl + 8);
        const __nv_bfloat16* ph0 = (const __nv_bfloat16*)&h0;
        const __nv_bfloat16* ph1 = (const __nv_bfloat16*)&h1;
        const __nv_bfloat16* pl0 = (const __nv_bfloat16*)&l0;
        const __nv_bfloat16* pl1 = (const __nv_bfloat16*)&l1;
        float d = 0.f;
        #pragma unroll
        for (int j = 0; j < 8; j++) {
            d = fmaf(qs[lane * 16 + j],     __bfloat162float(ph0[j]) + __bfloat162float(pl0[j]), d);
            d = fmaf(qs[lane * 16 + 8 + j], __bfloat162float(ph1[j]) + __bfloat162float(pl1[j]), d);
        }
        d = warpSum(d);
        if (lane == 0) s_val[ci] = d;
    }
    __syncthreads();

    // --- exact max over candidates ---
    float lm = (tid < cnt) ? s_val[tid] : -1e30f;
    lm = warpMax(lm);
    if (lane == 0) sh[w] = lm;
    __syncthreads();
    if (w == 0) {
        lm = (lane < 8) ? sh[lane] : -1e30f;
        lm = warpMax(lm);
        if (lane == 0) f_b = lm;
    }
    __syncthreads();
    float emax = f_b;

    // --- exp + Z (deterministic) ---
    float e = (tid < cnt) ? __expf(s_val[tid] - emax) : 0.f;
    float ps = warpSum(e);
    __syncthreads();
    if (lane == 0) sh[w] = ps;
    __syncthreads();
    if (w == 0) {
        ps = (lane < 8) ? sh[lane] : 0.f;
        ps = warpSum(ps);
        if (lane == 0) f_b = ps;
    }
    __syncthreads();
    float Z = f_b;
    float invZ = 1.f / Z;

    // --- compact kept list (weight >= PVW), warp-scan ---
    int k = (tid < cnt && e >= PVW * Z) ? 1 : 0;
    int incl2 = warpInclScan(k, lane);
    if (lane == 31) wtot[w] = incl2;
    __syncthreads();
    if (w == 0 && lane < 8) {
        int t = wtot[lane];
        #pragma unroll
        for (int o2 = 1; o2 < 8; o2 <<= 1) {
            int u = __shfl_up_sync(0xffu, t, o2);
            if (lane >= o2) t += u;
        }
        wtot[lane] = t;
    }
    __syncthreads();
    if (k) {
        int pos = ((w > 0) ? wtot[w - 1] : 0) + incl2 - 1;
        s_kidx[pos] = s_idx[tid];
        s_val[pos]  = e * invZ;
    }
    __syncthreads();
    int nk = wtot[7];

    // --- sparse PV (V^2 on the fly) ---
    int ch = tid * 2;
    float2 macc  = make_float2(0.f, 0.f);
    float2 m2acc = make_float2(0.f, 0.f);
    for (int e2 = 0; e2 < nk; e2++) {
        int m = s_kidx[e2];
        float ww = s_val[e2];
        size_t vb = ((size_t)(b * NPIX + m)) * CDIM + ch;
        float2 v = *(const float2*)(g_Vf + vb);
        macc.x  = fmaf(ww, v.x,       macc.x);  macc.y  = fmaf(ww, v.y,       macc.y);
        m2acc.x = fmaf(ww, v.x * v.x, m2acc.x); m2acc.y = fmaf(ww, v.y * v.y, m2acc.y);
    }
    size_t ob = ((size_t)(b * NPIX + n)) * CDIM + ch;
    *(float2*)(g_M  + ob) = macc;
    *(float2*)(g_M2 + ob) = m2acc;
}

// ---------------- 6) epilogue (coalesced along n) ----------------
__global__ void epilogue_kernel(const float* __restrict__ F_c, float* __restrict__ out) {
    __shared__ float shS[32][33];
    __shared__ float shM[32][33];
    int b = blockIdx.z;
    int n0 = blockIdx.x * 32, v0 = blockIdx.y * 32;
    int tx = threadIdx.x, ty = threadIdx.y;

    #pragma unroll
    for (int i = 0; i < 4; i++) {
        int n = n0 + ty + i * 8;
        int v = v0 + tx;
        size_t idx = ((size_t)(b * NPIX + n)) * CDIM + v;
        float m = g_M[idx], m2 = g_M2[idx];
        float var = m2 - m * m;
        shS[ty + i * 8][tx] = sqrtf(fmaxf(var, 0.f) + 1e-8f);
        shM[ty + i * 8][tx] = m;
    }
    __syncthreads();
    #pragma unroll
    for (int i = 0; i < 4; i++) {
        int v = v0 + ty + i * 8;
        int n = n0 + tx;
        float mean = g_mean[2][v], inv = g_inv[2][v];
        size_t fidx = ((size_t)(b * CDIM + v)) * NPIX + n;
        float fn = (F_c[fidx] - mean) * inv;
        out[fidx] = shS[tx][ty + i * 8] * fn + shM[tx][ty + i * 8];
    }
}

// ---------------- launch ----------------
extern "C" void kernel_launch(void* const* d_in, const int* in_sizes, int n_in,
                              void* d_out, int out_size) {
    const float* F_c      = (const float*)d_in[0];
    const float* F_s      = (const float*)d_in[1];
    const float* F_c_prev = (const float*)d_in[2];
    const float* F_s_prev = (const float*)d_in[3];
    const float* Wf = (const float*)d_in[4];
    const float* bf = (const float*)d_in[5];
    const float* Wg = (const float*)d_in[6];
    const float* bg = (const float*)d_in[7];
    const float* Wh = (const float*)d_in[8];
    const float* bh = (const float*)d_in[9];
    float* out = (float*)d_out;

    cudaFuncSetAttribute(mm2hh_kernel, cudaFuncAttributeMaxDynamicSharedMemorySize, MM_SMEM2);
    cudaFuncSetAttribute(projmma3_kernel, cudaFuncAttributeMaxDynamicSharedMemorySize, MM_SMEM4);

    stats_kernel<<<dim3(CDIM, 3), 256>>>(F_c_prev, F_s_prev, F_c);
    fold_kernel<<<dim3(CDIM, 3), 256>>>(Wf, bf, Wg, bg, Wh, bh);

    transpose_split_kernel<<<dim3(NPIX / 32, CDIM / 32, 12), dim3(32, 8)>>>(
        F_c_prev, F_s_prev, F_s);

    projmma3_kernel<<<dim3(NPIX / 128, CDIM / 128, 12), 256, MM_SMEM4>>>();

    mm2hh_kernel<<<dim3(NPIX / 128, NPIX / 128, BATCH), 256, MM_SMEM2>>>();
    attn_fused_kernel<<<BATCH * NPIX, 256>>>();

    epilogue_kernel<<<dim3(NPIX / 32, CDIM / 32, BATCH), dim3(32, 8)>>>(F_c, out);
}